// round 11
// baseline (speedup 1.0000x reference)
#include <cuda_runtime.h>
#include <math.h>

#define BB   16
#define CIN  64
#define COUT 64
#define HH   256
#define WW   256
#define NMODE 800        // 40 kx * 20 ky
#define NBI  1024        // B*CI
#define NBO  1024        // B*CO

__device__ float2 g_Xf[NMODE * NBI];       // [m][bi]  6.6 MB
__device__ float2 g_Yf[NBO * NMODE];       // [bo][m]  6.6 MB

// ---------------------------------------------------------------------------
// Kernel A: fused W-DFT + H-DFT for one (b,ci) image. 256 threads, 3 CTA/SM.
// Phase 1 (reflection + parity fold), register tiled as R8:
//   thread = (rp = t&127 -> rows rp and rp+128, kyh = t>>7 -> ky half).
//   Consumer written without temp arrays to fit the 84-reg budget.
//   h-fold (rows rp / rp+128) in registers -> Xsum/Xdif pitch-11 float4.
// Phase 2: conjugate-pair blocked H-DFT.
// ---------------------------------------------------------------------------
#define P1_KY5(SE, DE, SO, DO, TIDX)                                \
    {                                                               \
        _Pragma("unroll")                                           \
        for (int k = 0; k < 5; k++) {                               \
            float4 tv = tw4[(TIDX) + k];   /* broadcast */          \
            acc0[k].x = fmaf( (SE##0), tv.x, acc0[k].x);            \
            acc0[k].y = fmaf(-(DE##0), tv.y, acc0[k].y);            \
            acc0[k].z = fmaf( (DO##0), tv.z, acc0[k].z);            \
            acc0[k].w = fmaf(-(SO##0), tv.w, acc0[k].w);            \
            acc1[k].x = fmaf( (SE##1), tv.x, acc1[k].x);            \
            acc1[k].y = fmaf(-(DE##1), tv.y, acc1[k].y);            \
            acc1[k].z = fmaf( (DO##1), tv.z, acc1[k].z);            \
            acc1[k].w = fmaf(-(SO##1), tv.w, acc1[k].w);            \
        }                                                           \
    }

__global__ void __launch_bounds__(256, 3) stage12_fwd(const float* __restrict__ x) {
    extern __shared__ float smem[];
    float*  Ef  = smem;                            // [256*12]
    float*  Of  = smem + 3072;
    float*  EMf = smem + 6144;
    float*  OMf = smem + 9216;
    float4* tw4 = (float4*)(smem + 12288);         // [64][10]
    float2* eb  = (float2*)(smem + 14848);         // [256]
    float4* Xs4 = (float4*)smem;                   // [128][11] (phase-2 input)
    float4* Xd4 = Xs4 + 1408;

    const int bi  = blockIdx.x;
    const int t   = threadIdx.x;
    const int rp  = t & 127;
    const int kyh = t >> 7;                        // warp-uniform ky half

    for (int i = t; i < 640; i += 256) {
        int wi = i / 10 + 1, kk = i % 10;
        float s0, c0, s1, c1;
        sincospif((float)((2*kk    ) * wi) * (1.0f/128.0f), &s0, &c0);
        sincospif((float)((2*kk + 1) * wi) * (1.0f/128.0f), &s1, &c1);
        float hsc = (wi == 64) ? 0.5f : 1.0f;
        tw4[i] = make_float4(c0*hsc, s0*hsc, c1*hsc, s1*hsc);
    }
    {
        float s, c;
        sincospif((float)t * (1.0f/128.0f), &s, &c);
        eb[t] = make_float2(c, s);
    }

    const float* img = x + (size_t)bi * (HH*WW);

    float4 acc0[5], acc1[5];
    {
        float a0 = img[rp*WW],         b0 = img[rp*WW + 128];
        float a1 = img[(rp+128)*WW],   b1 = img[(rp+128)*WW + 128];
        float ue0 = a0 + b0, uo0 = a0 - b0;
        float ue1 = a1 + b1, uo1 = a1 - b1;
        #pragma unroll
        for (int k = 0; k < 5; k++) {
            acc0[k] = make_float4(ue0, 0.f, uo0, 0.f);   // w=0 term (c=1,s=0)
            acc1[k] = make_float4(ue1, 0.f, uo1, 0.f);
        }
    }

    for (int c = 0; c < 8; c++) {                  // chunks of 8 w, w = 1..64
        const int w0     = 1 + 8*c;
        const int mstart = 120 - 8*c;              // mirror window start
        __syncthreads();
        #pragma unroll
        for (int i = 0; i < 8; i++) {
            int idx = t + i*256;                   // 0..2047
            int r   = idx >> 3;
            int j   = idx & 7;
            const float* rpn = img + r * WW;
            float a1 = rpn[w0 + j],     b1 = rpn[w0 + j + 128];
            float a2 = rpn[mstart + j], b2 = rpn[mstart + j + 128];
            int s = r*12 + j;
            Ef[s]  = a1 + b1;  Of[s]  = a1 - b1;
            EMf[s] = a2 + b2;  OMf[s] = a2 - b2;
        }
        __syncthreads();

        const float4* E4  = (const float4*)Ef;
        const float4* O4  = (const float4*)Of;
        const float4* EM4 = (const float4*)EMf;
        const float4* OM4 = (const float4*)OMf;
        #pragma unroll
        for (int g = 0; g < 2; g++) {
            float4 e0  = E4 [rp*3 + g];
            float4 o0  = O4 [rp*3 + g];
            float4 em0 = EM4[rp*3 + (1-g)];
            float4 om0 = OM4[rp*3 + (1-g)];
            float4 e1  = E4 [(rp+128)*3 + g];
            float4 o1  = O4 [(rp+128)*3 + g];
            float4 em1 = EM4[(rp+128)*3 + (1-g)];
            float4 om1 = OM4[(rp+128)*3 + (1-g)];
            const int tb = (8*c + 4*g)*10 + kyh*5;

            // jj = 0: e.x pairs mirror .w
            {
                float se0 = e0.x + em0.w, de0 = e0.x - em0.w;
                float so0 = o0.x + om0.w, do0 = o0.x - om0.w;
                float se1 = e1.x + em1.w, de1 = e1.x - em1.w;
                float so1 = o1.x + om1.w, do1 = o1.x - om1.w;
                P1_KY5(se, de, so, do, tb)
            }
            // jj = 1: .y pairs .z
            {
                float se0 = e0.y + em0.z, de0 = e0.y - em0.z;
                float so0 = o0.y + om0.z, do0 = o0.y - om0.z;
                float se1 = e1.y + em1.z, de1 = e1.y - em1.z;
                float so1 = o1.y + om1.z, do1 = o1.y - om1.z;
                P1_KY5(se, de, so, do, tb + 10)
            }
            // jj = 2: .z pairs .y
            {
                float se0 = e0.z + em0.y, de0 = e0.z - em0.y;
                float so0 = o0.z + om0.y, do0 = o0.z - om0.y;
                float se1 = e1.z + em1.y, de1 = e1.z - em1.y;
                float so1 = o1.z + om1.y, do1 = o1.z - om1.y;
                P1_KY5(se, de, so, do, tb + 20)
            }
            // jj = 3: .w pairs .x
            {
                float se0 = e0.w + em0.x, de0 = e0.w - em0.x;
                float so0 = o0.w + om0.x, do0 = o0.w - om0.x;
                float se1 = e1.w + em1.x, de1 = e1.w - em1.x;
                float so1 = o1.w + om1.x, do1 = o1.w - om1.x;
                P1_KY5(se, de, so, do, tb + 30)
            }
        }
    }

    // h-fold in registers (rows rp / rp+128), store Xsum/Xdif at pitch 11
    __syncthreads();
    #pragma unroll
    for (int k = 0; k < 5; k++) {
        const int idx = rp*11 + kyh*5 + k;
        Xs4[idx] = make_float4(acc0[k].x + acc1[k].x, acc0[k].y + acc1[k].y,
                               acc0[k].z + acc1[k].z, acc0[k].w + acc1[k].w);
        Xd4[idx] = make_float4(acc0[k].x - acc1[k].x, acc0[k].y - acc1[k].y,
                               acc0[k].z - acc1[k].z, acc0[k].w - acc1[k].w);
    }
    __syncthreads();

    // Phase 2: conjugate-pair blocked H-DFT. 210 active threads.
    if (t < 210) {
        const int pr = t / 10;                      // 0..20
        const int kp = t % 10;

        if (pr == 0) {
            const float4* Xp = Xs4;
            float4 acc = make_float4(0.f, 0.f, 0.f, 0.f);
            #pragma unroll 8
            for (int h = 0; h < 128; h++) {
                float4 xv = Xp[h*11 + kp];
                acc.x += xv.x; acc.y += xv.y; acc.z += xv.z; acc.w += xv.w;
            }
            const int m0 = 2*kp;
            g_Xf[(size_t)m0     * NBI + bi] = make_float2(acc.x, acc.y);
            g_Xf[(size_t)(m0+1) * NBI + bi] = make_float2(acc.z, acc.w);
        } else if (pr == 20) {
            const float4* Xp = Xs4;                 // kx=236 even parity
            float4 acc = make_float4(0.f, 0.f, 0.f, 0.f);
            int p = 0;
            #pragma unroll 8
            for (int h = 0; h < 128; h++) {
                float2 e  = eb[p];
                p = (p + 236) & 255;
                float4 xv = Xp[h*11 + kp];
                acc.x = fmaf(xv.x, e.x, acc.x); acc.x = fmaf( xv.y, e.y, acc.x);
                acc.y = fmaf(xv.y, e.x, acc.y); acc.y = fmaf(-xv.x, e.y, acc.y);
                acc.z = fmaf(xv.z, e.x, acc.z); acc.z = fmaf( xv.w, e.y, acc.z);
                acc.w = fmaf(xv.w, e.x, acc.w); acc.w = fmaf(-xv.z, e.y, acc.w);
            }
            const int m0 = 20*20 + 2*kp;
            g_Xf[(size_t)m0     * NBI + bi] = make_float2(acc.x, acc.y);
            g_Xf[(size_t)(m0+1) * NBI + bi] = make_float2(acc.z, acc.w);
        } else {
            const float4* Xp = (pr & 1) ? Xd4 : Xs4;
            float4 aP = make_float4(0.f, 0.f, 0.f, 0.f);
            float4 aM = make_float4(0.f, 0.f, 0.f, 0.f);
            int p = 0;
            #pragma unroll 4
            for (int h = 0; h < 128; h++) {
                float2 e  = eb[p];
                p = (p + pr) & 255;
                float4 xv = Xp[h*11 + kp];
                aP.x = fmaf(xv.x, e.x, aP.x); aP.x = fmaf( xv.y, e.y, aP.x);
                aP.y = fmaf(xv.y, e.x, aP.y); aP.y = fmaf(-xv.x, e.y, aP.y);
                aP.z = fmaf(xv.z, e.x, aP.z); aP.z = fmaf( xv.w, e.y, aP.z);
                aP.w = fmaf(xv.w, e.x, aP.w); aP.w = fmaf(-xv.z, e.y, aP.w);
                aM.x = fmaf(xv.x, e.x, aM.x); aM.x = fmaf(-xv.y, e.y, aM.x);
                aM.y = fmaf(xv.y, e.x, aM.y); aM.y = fmaf( xv.x, e.y, aM.y);
                aM.z = fmaf(xv.z, e.x, aM.z); aM.z = fmaf(-xv.w, e.y, aM.z);
                aM.w = fmaf(xv.w, e.x, aM.w); aM.w = fmaf( xv.z, e.y, aM.w);
            }
            const int mP = pr*20 + 2*kp;
            const int mM = (40 - pr)*20 + 2*kp;
            g_Xf[(size_t)mP     * NBI + bi] = make_float2(aP.x, aP.y);
            g_Xf[(size_t)(mP+1) * NBI + bi] = make_float2(aP.z, aP.w);
            g_Xf[(size_t)mM     * NBI + bi] = make_float2(aM.x, aM.y);
            g_Xf[(size_t)(mM+1) * NBI + bi] = make_float2(aM.z, aM.w);
        }
    }
}

// ---------------------------------------------------------------------------
// Stage 3: channel mix, 2 modes per block. (unchanged)
// ---------------------------------------------------------------------------
__global__ void __launch_bounds__(256) stage3_mix(const float* __restrict__ w1re,
                                                 const float* __restrict__ w1im,
                                                 const float* __restrict__ w2re,
                                                 const float* __restrict__ w2im) {
    extern __shared__ float smem3[];
    float4* Ws  = (float4*)smem3;                 // [4096]
    float2* Xs0 = (float2*)(smem3 + 16384);       // [1024]
    float2* Xs1 = (float2*)(smem3 + 18432);       // [1024]

    const int bq  = blockIdx.x;                   // 0..399
    const int t   = threadIdx.x;
    const int j   = bq / 10;
    const int kyg = bq % 10;
    const int m0  = j*20 + 2*kyg;

    const float* wre; const float* wim; int off;
    if (j < 20) { wre = w1re; wim = w1im; off = j*20 + 2*kyg; }
    else        { wre = w2re; wim = w2im; off = (j-20)*20 + 2*kyg; }

    for (int io = t; io < 4096; io += 256) {
        float2 r2 = *(const float2*)(wre + (size_t)io*400 + off);
        float2 i2 = *(const float2*)(wim + (size_t)io*400 + off);
        Ws[io] = make_float4(r2.x, i2.x, r2.y, i2.y);
    }
    for (int i = t; i < 1024; i += 256) {
        Xs0[i] = g_Xf[(size_t)m0     * NBI + i];
        Xs1[i] = g_Xf[(size_t)(m0+1) * NBI + i];
    }
    __syncthreads();

    const int o  = t & 63;
    const int xb = (t >> 6) << 6;
    float a0R[4], a0I[4], a1R[4], a1I[4];
    #pragma unroll
    for (int k = 0; k < 4; k++) { a0R[k]=0.f; a0I[k]=0.f; a1R[k]=0.f; a1I[k]=0.f; }

    #pragma unroll 4
    for (int i = 0; i < 64; i++) {
        float4 wv = Ws[i*64 + o];
        #pragma unroll
        for (int k = 0; k < 4; k++) {
            float2 x0 = Xs0[xb + k*256 + i];
            a0R[k] = fmaf(x0.x, wv.x, a0R[k]); a0R[k] = fmaf(-x0.y, wv.y, a0R[k]);
            a0I[k] = fmaf(x0.x, wv.y, a0I[k]); a0I[k] = fmaf( x0.y, wv.x, a0I[k]);
            float2 x1 = Xs1[xb + k*256 + i];
            a1R[k] = fmaf(x1.x, wv.z, a1R[k]); a1R[k] = fmaf(-x1.y, wv.w, a1R[k]);
            a1I[k] = fmaf(x1.x, wv.w, a1I[k]); a1I[k] = fmaf( x1.y, wv.z, a1I[k]);
        }
    }
    float4* Y4 = (float4*)g_Yf;
    #pragma unroll
    for (int k = 0; k < 4; k++) {
        size_t base = ((size_t)(t + k*256) * NMODE + m0) >> 1;
        Y4[base] = make_float4(a0R[k], a0I[k], a1R[k], a1I[k]);
    }
}

// ---------------------------------------------------------------------------
// Kernel B: fused inverse H-DFT + c2r. (unchanged)
// ---------------------------------------------------------------------------
__global__ void __launch_bounds__(256, 2) stage45_bwd(float* __restrict__ out) {
    extern __shared__ float smemb[];
    float2* Yfs = (float2*)smemb;                 // [800]
    float2* eb  = (float2*)(smemb + 1600);        // [256]
    float2* Ys  = (float2*)smemb;                 // [256][20] (overlap)

    const int bo = blockIdx.x;
    const int t  = threadIdx.x;

    for (int i = t; i < NMODE; i += 256) Yfs[i] = g_Yf[(size_t)bo * NMODE + i];
    {
        float s, c;
        sincospif((float)t * (1.0f/128.0f), &s, &c);
        eb[t] = make_float2(c, s);
    }
    __syncthreads();

    // Phase A
    {
        const int hh     = t & 127;
        const int kybase = (t >> 7) * 10;

        float aER[10], aEI[10], aOR[10], aOI[10];
        #pragma unroll
        for (int k = 0; k < 10; k++) { aER[k]=0.f; aEI[k]=0.f; aOR[k]=0.f; aOI[k]=0.f; }

        for (int j2 = 0; j2 < 20; j2++) {
            const int j0  = 2*j2;
            const int kx0 = j0 + ((j0 >= 20) ? 216 : 0);
            {
                float2 e = eb[(kx0 * hh) & 255];
                const float4* Y4 = (const float4*)(Yfs + j0*20 + kybase);
                #pragma unroll
                for (int k = 0; k < 5; k++) {
                    float4 yv = Y4[k];
                    aER[2*k  ] = fmaf(yv.x, e.x, aER[2*k  ]); aER[2*k  ] = fmaf(-yv.y, e.y, aER[2*k  ]);
                    aEI[2*k  ] = fmaf(yv.x, e.y, aEI[2*k  ]); aEI[2*k  ] = fmaf( yv.y, e.x, aEI[2*k  ]);
                    aER[2*k+1] = fmaf(yv.z, e.x, aER[2*k+1]); aER[2*k+1] = fmaf(-yv.w, e.y, aER[2*k+1]);
                    aEI[2*k+1] = fmaf(yv.z, e.y, aEI[2*k+1]); aEI[2*k+1] = fmaf( yv.w, e.x, aEI[2*k+1]);
                }
            }
            {
                float2 e = eb[((kx0+1) * hh) & 255];
                const float4* Y4 = (const float4*)(Yfs + (j0+1)*20 + kybase);
                #pragma unroll
                for (int k = 0; k < 5; k++) {
                    float4 yv = Y4[k];
                    aOR[2*k  ] = fmaf(yv.x, e.x, aOR[2*k  ]); aOR[2*k  ] = fmaf(-yv.y, e.y, aOR[2*k  ]);
                    aOI[2*k  ] = fmaf(yv.x, e.y, aOI[2*k  ]); aOI[2*k  ] = fmaf( yv.y, e.x, aOI[2*k  ]);
                    aOR[2*k+1] = fmaf(yv.z, e.x, aOR[2*k+1]); aOR[2*k+1] = fmaf(-yv.w, e.y, aOR[2*k+1]);
                    aOI[2*k+1] = fmaf(yv.z, e.y, aOI[2*k+1]); aOI[2*k+1] = fmaf( yv.w, e.x, aOI[2*k+1]);
                }
            }
        }

        __syncthreads();
        const float sc1 = 1.0f / 65536.0f;
        const float sc2 = 2.0f / 65536.0f;
        #pragma unroll
        for (int k = 0; k < 10; k++) {
            int ky  = kybase + k;
            float s = (ky == 0) ? sc1 : sc2;
            Ys[ (t & 127)       *20 + ky] = make_float2((aER[k] + aOR[k])*s, (aEI[k] + aOI[k])*s);
            Ys[((t & 127) + 128)*20 + ky] = make_float2((aER[k] - aOR[k])*s, (aEI[k] - aOI[k])*s);
        }
        __syncthreads();
    }

    // Phase B
    {
        const int w  = t & 63;
        const int qr = t >> 6;

        float cc[20], ss[20];
        #pragma unroll
        for (int ky = 0; ky < 20; ky++) {
            float s, c;
            sincospif((float)(ky * w) * (1.0f/128.0f), &s, &c);
            cc[ky] = c; ss[ky] = s;
        }

        float* outb = out + (size_t)bo * (HH*WW);
        const float4* y4 = (const float4*)Ys;

        #pragma unroll 2
        for (int rr = 0; rr < 64; rr++) {
            const int r = qr*64 + rr;
            float P0=0.f, P1=0.f, P2=0.f, P3=0.f, Q1=0.f, Q3=0.f;
            #pragma unroll
            for (int qq = 0; qq < 5; qq++) {
                {
                    float4 yv = y4[r*10 + 2*qq];
                    const int k0 = 4*qq, k1 = 4*qq + 1;
                    P0 = fmaf(yv.x, cc[k0], P0); P0 = fmaf(-yv.y, ss[k0], P0);
                    P1 = fmaf(yv.z, cc[k1], P1); P1 = fmaf(-yv.w, ss[k1], P1);
                    Q1 = fmaf(yv.z, ss[k1], Q1); Q1 = fmaf( yv.w, cc[k1], Q1);
                }
                {
                    float4 yv = y4[r*10 + 2*qq + 1];
                    const int k2 = 4*qq + 2, k3 = 4*qq + 3;
                    P2 = fmaf(yv.x, cc[k2], P2); P2 = fmaf(-yv.y, ss[k2], P2);
                    P3 = fmaf(yv.z, cc[k3], P3); P3 = fmaf(-yv.w, ss[k3], P3);
                    Q3 = fmaf(yv.z, ss[k3], Q3); Q3 = fmaf( yv.w, cc[k3], Q3);
                }
            }
            outb[r*256 + w      ] = P0 + P1 + P2 + P3;
            outb[r*256 + w +  64] = P0 - Q1 - P2 + Q3;
            outb[r*256 + w + 128] = P0 - P1 + P2 - P3;
            outb[r*256 + w + 192] = P0 + Q1 - P2 - Q3;
        }
    }
}

// ---------------------------------------------------------------------------
extern "C" void kernel_launch(void* const* d_in, const int* in_sizes, int n_in,
                              void* d_out, int out_size) {
    const float* x    = (const float*)d_in[0];
    const float* w1re = (const float*)d_in[1];
    const float* w1im = (const float*)d_in[2];
    const float* w2re = (const float*)d_in[3];
    const float* w2im = (const float*)d_in[4];
    float* out = (float*)d_out;

    const int sA = 61440;
    const int s3 = 81920;
    const int sB = 40960;
    cudaFuncSetAttribute(stage12_fwd, cudaFuncAttributeMaxDynamicSharedMemorySize, sA);
    cudaFuncSetAttribute(stage3_mix,  cudaFuncAttributeMaxDynamicSharedMemorySize, s3);
    cudaFuncSetAttribute(stage45_bwd, cudaFuncAttributeMaxDynamicSharedMemorySize, sB);

    stage12_fwd<<<NBI, 256, sA>>>(x);
    stage3_mix <<<400, 256, s3>>>(w1re, w1im, w2re, w2im);
    stage45_bwd<<<NBO, 256, sB>>>(out);
}

// round 12
// speedup vs baseline: 1.1205x; 1.1205x over previous
#include <cuda_runtime.h>
#include <math.h>

#define BB   16
#define CIN  64
#define COUT 64
#define HH   256
#define WW   256
#define NMODE 800        // 40 kx * 20 ky
#define NBI  1024        // B*CI
#define NBO  1024        // B*CO

__device__ float2 g_Xf[NMODE * NBI];       // [m][bi]  6.6 MB
__device__ float2 g_Yf[NBO * NMODE];       // [bo][m]  6.6 MB

// ---------------------------------------------------------------------------
// Kernel A: fused W-DFT + H-DFT for one (b,ci) image. 256 threads, 2 CTA/SM.
// (R8 configuration restored verbatim: best measured 132.7 us.)
// ---------------------------------------------------------------------------
__global__ void __launch_bounds__(256, 2) stage12_fwd(const float* __restrict__ x) {
    extern __shared__ float smem[];
    float*  Ef  = smem;                            // [256*12]
    float*  Of  = smem + 3072;
    float*  EMf = smem + 6144;
    float*  OMf = smem + 9216;
    float4* tw4 = (float4*)(smem + 12288);         // [64][10]
    float2* eb  = (float2*)(smem + 14848);         // [256]
    float4* Xs4 = (float4*)smem;                   // [128][11] (phase-2 input)
    float4* Xd4 = Xs4 + 1408;

    const int bi  = blockIdx.x;
    const int t   = threadIdx.x;
    const int rp  = t & 127;
    const int kyh = t >> 7;                        // warp-uniform ky half

    // twiddle tables: tw4[(w-1)*10+kk] = (c_{2kk},s_{2kk},c_{2kk+1},s_{2kk+1}) * (w==64?0.5:1)
    for (int i = t; i < 640; i += 256) {
        int wi = i / 10 + 1, kk = i % 10;
        float s0, c0, s1, c1;
        sincospif((float)((2*kk    ) * wi) * (1.0f/128.0f), &s0, &c0);
        sincospif((float)((2*kk + 1) * wi) * (1.0f/128.0f), &s1, &c1);
        float hsc = (wi == 64) ? 0.5f : 1.0f;
        tw4[i] = make_float4(c0*hsc, s0*hsc, c1*hsc, s1*hsc);
    }
    {
        float s, c;
        sincospif((float)t * (1.0f/128.0f), &s, &c);
        eb[t] = make_float2(c, s);
    }

    const float* img = x + (size_t)bi * (HH*WW);

    // acc[k] covers ky pair (10*kyh+2k, 10*kyh+2k+1) as (Re,Ie,Ro,Io); rows rp / rp+128
    float4 acc0[5], acc1[5];
    {
        float a0 = img[rp*WW],         b0 = img[rp*WW + 128];
        float a1 = img[(rp+128)*WW],   b1 = img[(rp+128)*WW + 128];
        float ue0 = a0 + b0, uo0 = a0 - b0;
        float ue1 = a1 + b1, uo1 = a1 - b1;
        #pragma unroll
        for (int k = 0; k < 5; k++) {
            acc0[k] = make_float4(ue0, 0.f, uo0, 0.f);   // w=0 term (c=1,s=0)
            acc1[k] = make_float4(ue1, 0.f, uo1, 0.f);
        }
    }

    for (int c = 0; c < 8; c++) {                  // chunks of 8 w, w = 1..64
        const int w0     = 1 + 8*c;
        const int mstart = 120 - 8*c;              // mirror window start
        __syncthreads();
        #pragma unroll
        for (int i = 0; i < 8; i++) {
            int idx = t + i*256;                   // 0..2047
            int r   = idx >> 3;
            int j   = idx & 7;
            const float* rpn = img + r * WW;
            float a1 = rpn[w0 + j],     b1 = rpn[w0 + j + 128];
            float a2 = rpn[mstart + j], b2 = rpn[mstart + j + 128];
            int s = r*12 + j;
            Ef[s]  = a1 + b1;  Of[s]  = a1 - b1;
            EMf[s] = a2 + b2;  OMf[s] = a2 - b2;
        }
        __syncthreads();

        const float4* E4  = (const float4*)Ef;
        const float4* O4  = (const float4*)Of;
        const float4* EM4 = (const float4*)EMf;
        const float4* OM4 = (const float4*)OMf;
        #pragma unroll
        for (int g = 0; g < 2; g++) {
            float4 e0  = E4 [rp*3 + g];
            float4 o0  = O4 [rp*3 + g];
            float4 em0 = EM4[rp*3 + (1-g)];
            float4 om0 = OM4[rp*3 + (1-g)];
            float4 e1  = E4 [(rp+128)*3 + g];
            float4 o1  = O4 [(rp+128)*3 + g];
            float4 em1 = EM4[(rp+128)*3 + (1-g)];
            float4 om1 = OM4[(rp+128)*3 + (1-g)];
            const float ev0[4]  = {e0.x,  e0.y,  e0.z,  e0.w};
            const float ov0[4]  = {o0.x,  o0.y,  o0.z,  o0.w};
            const float emv0[4] = {em0.x, em0.y, em0.z, em0.w};
            const float omv0[4] = {om0.x, om0.y, om0.z, om0.w};
            const float ev1[4]  = {e1.x,  e1.y,  e1.z,  e1.w};
            const float ov1[4]  = {o1.x,  o1.y,  o1.z,  o1.w};
            const float emv1[4] = {em1.x, em1.y, em1.z, em1.w};
            const float omv1[4] = {om1.x, om1.y, om1.z, om1.w};
            const int tb = (8*c + 4*g)*10 + kyh*5;   // tw index base for jj=0
            #pragma unroll
            for (int jj = 0; jj < 4; jj++) {
                const float se0 = ev0[jj] + emv0[3-jj];
                const float de0 = ev0[jj] - emv0[3-jj];
                const float so0 = ov0[jj] + omv0[3-jj];
                const float do0 = ov0[jj] - omv0[3-jj];
                const float se1 = ev1[jj] + emv1[3-jj];
                const float de1 = ev1[jj] - emv1[3-jj];
                const float so1 = ov1[jj] + omv1[3-jj];
                const float do1 = ov1[jj] - omv1[3-jj];
                #pragma unroll
                for (int k = 0; k < 5; k++) {
                    float4 tv = tw4[tb + jj*10 + k];   // broadcast
                    acc0[k].x = fmaf( se0, tv.x, acc0[k].x);
                    acc0[k].y = fmaf(-de0, tv.y, acc0[k].y);
                    acc0[k].z = fmaf( do0, tv.z, acc0[k].z);
                    acc0[k].w = fmaf(-so0, tv.w, acc0[k].w);
                    acc1[k].x = fmaf( se1, tv.x, acc1[k].x);
                    acc1[k].y = fmaf(-de1, tv.y, acc1[k].y);
                    acc1[k].z = fmaf( do1, tv.z, acc1[k].z);
                    acc1[k].w = fmaf(-so1, tv.w, acc1[k].w);
                }
            }
        }
    }

    // h-fold in registers (rows rp / rp+128), store Xsum/Xdif at pitch 11
    __syncthreads();
    #pragma unroll
    for (int k = 0; k < 5; k++) {
        const int idx = rp*11 + kyh*5 + k;
        Xs4[idx] = make_float4(acc0[k].x + acc1[k].x, acc0[k].y + acc1[k].y,
                               acc0[k].z + acc1[k].z, acc0[k].w + acc1[k].w);
        Xd4[idx] = make_float4(acc0[k].x - acc1[k].x, acc0[k].y - acc1[k].y,
                               acc0[k].z - acc1[k].z, acc0[k].w - acc1[k].w);
    }
    __syncthreads();

    // Phase 2: conjugate-pair blocked H-DFT. 210 active threads.
    if (t < 210) {
        const int pr = t / 10;                      // 0..20
        const int kp = t % 10;

        if (pr == 0) {
            const float4* Xp = Xs4;
            float4 acc = make_float4(0.f, 0.f, 0.f, 0.f);
            #pragma unroll 8
            for (int h = 0; h < 128; h++) {
                float4 xv = Xp[h*11 + kp];
                acc.x += xv.x; acc.y += xv.y; acc.z += xv.z; acc.w += xv.w;
            }
            const int m0 = 2*kp;
            g_Xf[(size_t)m0     * NBI + bi] = make_float2(acc.x, acc.y);
            g_Xf[(size_t)(m0+1) * NBI + bi] = make_float2(acc.z, acc.w);
        } else if (pr == 20) {
            const float4* Xp = Xs4;                 // kx=236 even parity
            float4 acc = make_float4(0.f, 0.f, 0.f, 0.f);
            int p = 0;
            #pragma unroll 8
            for (int h = 0; h < 128; h++) {
                float2 e  = eb[p];
                p = (p + 236) & 255;
                float4 xv = Xp[h*11 + kp];
                acc.x = fmaf(xv.x, e.x, acc.x); acc.x = fmaf( xv.y, e.y, acc.x);
                acc.y = fmaf(xv.y, e.x, acc.y); acc.y = fmaf(-xv.x, e.y, acc.y);
                acc.z = fmaf(xv.z, e.x, acc.z); acc.z = fmaf( xv.w, e.y, acc.z);
                acc.w = fmaf(xv.w, e.x, acc.w); acc.w = fmaf(-xv.z, e.y, acc.w);
            }
            const int m0 = 20*20 + 2*kp;
            g_Xf[(size_t)m0     * NBI + bi] = make_float2(acc.x, acc.y);
            g_Xf[(size_t)(m0+1) * NBI + bi] = make_float2(acc.z, acc.w);
        } else {
            const float4* Xp = (pr & 1) ? Xd4 : Xs4;
            float4 aP = make_float4(0.f, 0.f, 0.f, 0.f);
            float4 aM = make_float4(0.f, 0.f, 0.f, 0.f);
            int p = 0;
            #pragma unroll 4
            for (int h = 0; h < 128; h++) {
                float2 e  = eb[p];
                p = (p + pr) & 255;
                float4 xv = Xp[h*11 + kp];
                aP.x = fmaf(xv.x, e.x, aP.x); aP.x = fmaf( xv.y, e.y, aP.x);
                aP.y = fmaf(xv.y, e.x, aP.y); aP.y = fmaf(-xv.x, e.y, aP.y);
                aP.z = fmaf(xv.z, e.x, aP.z); aP.z = fmaf( xv.w, e.y, aP.z);
                aP.w = fmaf(xv.w, e.x, aP.w); aP.w = fmaf(-xv.z, e.y, aP.w);
                aM.x = fmaf(xv.x, e.x, aM.x); aM.x = fmaf(-xv.y, e.y, aM.x);
                aM.y = fmaf(xv.y, e.x, aM.y); aM.y = fmaf( xv.x, e.y, aM.y);
                aM.z = fmaf(xv.z, e.x, aM.z); aM.z = fmaf(-xv.w, e.y, aM.z);
                aM.w = fmaf(xv.w, e.x, aM.w); aM.w = fmaf( xv.z, e.y, aM.w);
            }
            const int mP = pr*20 + 2*kp;
            const int mM = (40 - pr)*20 + 2*kp;
            g_Xf[(size_t)mP     * NBI + bi] = make_float2(aP.x, aP.y);
            g_Xf[(size_t)(mP+1) * NBI + bi] = make_float2(aP.z, aP.w);
            g_Xf[(size_t)mM     * NBI + bi] = make_float2(aM.x, aM.y);
            g_Xf[(size_t)(mM+1) * NBI + bi] = make_float2(aM.z, aM.w);
        }
    }
}

// ---------------------------------------------------------------------------
// Stage 3: channel mix, 2 modes per block. (unchanged)
// ---------------------------------------------------------------------------
__global__ void __launch_bounds__(256) stage3_mix(const float* __restrict__ w1re,
                                                 const float* __restrict__ w1im,
                                                 const float* __restrict__ w2re,
                                                 const float* __restrict__ w2im) {
    extern __shared__ float smem3[];
    float4* Ws  = (float4*)smem3;                 // [4096]
    float2* Xs0 = (float2*)(smem3 + 16384);       // [1024]
    float2* Xs1 = (float2*)(smem3 + 18432);       // [1024]

    const int bq  = blockIdx.x;                   // 0..399
    const int t   = threadIdx.x;
    const int j   = bq / 10;
    const int kyg = bq % 10;
    const int m0  = j*20 + 2*kyg;

    const float* wre; const float* wim; int off;
    if (j < 20) { wre = w1re; wim = w1im; off = j*20 + 2*kyg; }
    else        { wre = w2re; wim = w2im; off = (j-20)*20 + 2*kyg; }

    for (int io = t; io < 4096; io += 256) {
        float2 r2 = *(const float2*)(wre + (size_t)io*400 + off);
        float2 i2 = *(const float2*)(wim + (size_t)io*400 + off);
        Ws[io] = make_float4(r2.x, i2.x, r2.y, i2.y);
    }
    for (int i = t; i < 1024; i += 256) {
        Xs0[i] = g_Xf[(size_t)m0     * NBI + i];
        Xs1[i] = g_Xf[(size_t)(m0+1) * NBI + i];
    }
    __syncthreads();

    const int o  = t & 63;
    const int xb = (t >> 6) << 6;
    float a0R[4], a0I[4], a1R[4], a1I[4];
    #pragma unroll
    for (int k = 0; k < 4; k++) { a0R[k]=0.f; a0I[k]=0.f; a1R[k]=0.f; a1I[k]=0.f; }

    #pragma unroll 4
    for (int i = 0; i < 64; i++) {
        float4 wv = Ws[i*64 + o];
        #pragma unroll
        for (int k = 0; k < 4; k++) {
            float2 x0 = Xs0[xb + k*256 + i];
            a0R[k] = fmaf(x0.x, wv.x, a0R[k]); a0R[k] = fmaf(-x0.y, wv.y, a0R[k]);
            a0I[k] = fmaf(x0.x, wv.y, a0I[k]); a0I[k] = fmaf( x0.y, wv.x, a0I[k]);
            float2 x1 = Xs1[xb + k*256 + i];
            a1R[k] = fmaf(x1.x, wv.z, a1R[k]); a1R[k] = fmaf(-x1.y, wv.w, a1R[k]);
            a1I[k] = fmaf(x1.x, wv.w, a1I[k]); a1I[k] = fmaf( x1.y, wv.z, a1I[k]);
        }
    }
    float4* Y4 = (float4*)g_Yf;
    #pragma unroll
    for (int k = 0; k < 4; k++) {
        size_t base = ((size_t)(t + k*256) * NMODE + m0) >> 1;
        Y4[base] = make_float4(a0R[k], a0I[k], a1R[k], a1I[k]);
    }
}

// ---------------------------------------------------------------------------
// Kernel B: fused inverse H-DFT + c2r. 256 threads, 3 CTA/SM.
// Phase A (NEW): conjugate-pair blocked. For kx pair (pr, 256-pr):
//   Yp e^{i th} + Ym e^{-i th} = (S.re c - D.im s) + i (D.re s + S.im c),
//   S = Yp+Ym, D = Yp-Ym precomputed per block (h-independent) -> 4 FMA
//   per (pair, ky) instead of 8. kx=0 -> accumulator init; kx=236 lone.
//   h-parity fold (aE/aO by pr parity) unchanged.
// Phase B: unchanged quarter-rotation c2r.
// smem (floats):
//   Ys   [0,10240)        float2[256][20] (Yfs raw occupies [0,1600) first)
//   SD4  [10240,11760)    float4[19*20]  (Sre,Sim,Dre,Dim)
//   j0   [11760,11800)    float2[20]     Yf[kx=0]
//   j20  [11800,11840)    float2[20]     Yf[kx=236]
//   eb   [11840,12352)    float2[256]
// ---------------------------------------------------------------------------
__global__ void __launch_bounds__(256, 3) stage45_bwd(float* __restrict__ out) {
    extern __shared__ float smemb[];
    float2* Yfs = (float2*)smemb;                  // [800] raw (dead after prep)
    float2* Ys  = (float2*)smemb;                  // [256][20] (written post phase A)
    float4* SD4 = (float4*)(smemb + 10240);        // [380]
    float2* j0r = (float2*)(smemb + 11760);        // [20]
    float2* j20r= (float2*)(smemb + 11800);        // [20]
    float2* eb  = (float2*)(smemb + 11840);        // [256]

    const int bo = blockIdx.x;
    const int t  = threadIdx.x;

    for (int i = t; i < NMODE; i += 256) Yfs[i] = g_Yf[(size_t)bo * NMODE + i];
    {
        float s, c;
        sincospif((float)t * (1.0f/128.0f), &s, &c);
        eb[t] = make_float2(c, s);
    }
    __syncthreads();

    // prep: S/D for pairs pr=1..19, singles j=0 (kx=0), j=20 (kx=236)
    for (int i = t; i < 380; i += 256) {
        int pr = i / 20 + 1;
        int ky = i % 20;
        float2 Yp = Yfs[pr*20 + ky];
        float2 Ym = Yfs[(40 - pr)*20 + ky];
        SD4[i] = make_float4(Yp.x + Ym.x, Yp.y + Ym.y, Yp.x - Ym.x, Yp.y - Ym.y);
    }
    if (t < 20) { j0r[t] = Yfs[t]; j20r[t] = Yfs[400 + t]; }
    __syncthreads();

    // Phase A
    {
        const int hh     = t & 127;
        const int kybase = (t >> 7) * 10;

        float aER[10], aEI[10], aOR[10], aOI[10];
        #pragma unroll
        for (int k = 0; k < 10; k++) {
            float2 y0 = j0r[kybase + k];           // kx=0: e=1 (even parity)
            aER[k] = y0.x; aEI[k] = y0.y;
            aOR[k] = 0.f;  aOI[k] = 0.f;
        }

        // odd pr pairs: 1,3,...,19 -> O accumulators
        #pragma unroll 2
        for (int pp = 0; pp < 10; pp++) {
            const int pr = 2*pp + 1;
            float2 e = eb[(pr * hh) & 255];
            const float4* SDp = SD4 + (pr - 1)*20 + kybase;
            #pragma unroll
            for (int k = 0; k < 10; k++) {
                float4 f = SDp[k];                 // broadcast
                aOR[k] = fmaf(f.x, e.x, aOR[k]); aOR[k] = fmaf(-f.w, e.y, aOR[k]);
                aOI[k] = fmaf(f.z, e.y, aOI[k]); aOI[k] = fmaf( f.y, e.x, aOI[k]);
            }
        }
        // even pr pairs: 2,4,...,18 -> E accumulators
        #pragma unroll 2
        for (int pp = 1; pp <= 9; pp++) {
            const int pr = 2*pp;
            float2 e = eb[(pr * hh) & 255];
            const float4* SDp = SD4 + (pr - 1)*20 + kybase;
            #pragma unroll
            for (int k = 0; k < 10; k++) {
                float4 f = SDp[k];                 // broadcast
                aER[k] = fmaf(f.x, e.x, aER[k]); aER[k] = fmaf(-f.w, e.y, aER[k]);
                aEI[k] = fmaf(f.z, e.y, aEI[k]); aEI[k] = fmaf( f.y, e.x, aEI[k]);
            }
        }
        // lone kx=236 (even parity)
        {
            float2 e = eb[(236 * hh) & 255];
            #pragma unroll
            for (int k = 0; k < 10; k++) {
                float2 y = j20r[kybase + k];       // broadcast
                aER[k] = fmaf(y.x, e.x, aER[k]); aER[k] = fmaf(-y.y, e.y, aER[k]);
                aEI[k] = fmaf(y.x, e.y, aEI[k]); aEI[k] = fmaf( y.y, e.x, aEI[k]);
            }
        }

        // scaled h-fold output (Ys region disjoint from SD/eb; Yfs raw is dead)
        const float sc1 = 1.0f / 65536.0f;
        const float sc2 = 2.0f / 65536.0f;
        #pragma unroll
        for (int k = 0; k < 10; k++) {
            int ky  = kybase + k;
            float s = (ky == 0) ? sc1 : sc2;
            Ys[ hh       *20 + ky] = make_float2((aER[k] + aOR[k])*s, (aEI[k] + aOI[k])*s);
            Ys[(hh + 128)*20 + ky] = make_float2((aER[k] - aOR[k])*s, (aEI[k] - aOI[k])*s);
        }
        __syncthreads();
    }

    // Phase B (unchanged)
    {
        const int w  = t & 63;
        const int qr = t >> 6;

        float cc[20], ss[20];
        #pragma unroll
        for (int ky = 0; ky < 20; ky++) {
            float s, c;
            sincospif((float)(ky * w) * (1.0f/128.0f), &s, &c);
            cc[ky] = c; ss[ky] = s;
        }

        float* outb = out + (size_t)bo * (HH*WW);
        const float4* y4 = (const float4*)Ys;

        #pragma unroll 2
        for (int rr = 0; rr < 64; rr++) {
            const int r = qr*64 + rr;
            float P0=0.f, P1=0.f, P2=0.f, P3=0.f, Q1=0.f, Q3=0.f;
            #pragma unroll
            for (int qq = 0; qq < 5; qq++) {
                {
                    float4 yv = y4[r*10 + 2*qq];
                    const int k0 = 4*qq, k1 = 4*qq + 1;
                    P0 = fmaf(yv.x, cc[k0], P0); P0 = fmaf(-yv.y, ss[k0], P0);
                    P1 = fmaf(yv.z, cc[k1], P1); P1 = fmaf(-yv.w, ss[k1], P1);
                    Q1 = fmaf(yv.z, ss[k1], Q1); Q1 = fmaf( yv.w, cc[k1], Q1);
                }
                {
                    float4 yv = y4[r*10 + 2*qq + 1];
                    const int k2 = 4*qq + 2, k3 = 4*qq + 3;
                    P2 = fmaf(yv.x, cc[k2], P2); P2 = fmaf(-yv.y, ss[k2], P2);
                    P3 = fmaf(yv.z, cc[k3], P3); P3 = fmaf(-yv.w, ss[k3], P3);
                    Q3 = fmaf(yv.z, ss[k3], Q3); Q3 = fmaf( yv.w, cc[k3], Q3);
                }
            }
            outb[r*256 + w      ] = P0 + P1 + P2 + P3;
            outb[r*256 + w +  64] = P0 - Q1 - P2 + Q3;
            outb[r*256 + w + 128] = P0 - P1 + P2 - P3;
            outb[r*256 + w + 192] = P0 + Q1 - P2 - Q3;
        }
    }
}

// ---------------------------------------------------------------------------
extern "C" void kernel_launch(void* const* d_in, const int* in_sizes, int n_in,
                              void* d_out, int out_size) {
    const float* x    = (const float*)d_in[0];
    const float* w1re = (const float*)d_in[1];
    const float* w1im = (const float*)d_in[2];
    const float* w2re = (const float*)d_in[3];
    const float* w2im = (const float*)d_in[4];
    float* out = (float*)d_out;

    const int sA = 61440;
    const int s3 = 81920;
    const int sB = 49408;   // Ys 40960 + SD 6080 + j0/j20 320 + eb 2048
    cudaFuncSetAttribute(stage12_fwd, cudaFuncAttributeMaxDynamicSharedMemorySize, sA);
    cudaFuncSetAttribute(stage3_mix,  cudaFuncAttributeMaxDynamicSharedMemorySize, s3);
    cudaFuncSetAttribute(stage45_bwd, cudaFuncAttributeMaxDynamicSharedMemorySize, sB);

    stage12_fwd<<<NBI, 256, sA>>>(x);
    stage3_mix <<<400, 256, s3>>>(w1re, w1im, w2re, w2im);
    stage45_bwd<<<NBO, 256, sB>>>(out);
}